// round 3
// baseline (speedup 1.0000x reference)
#include <cuda_runtime.h>
#include <cuda_bf16.h>

// LinearPatchMerger: fused 2x2 patch-merge gather + SGEMM.
// Geometry is fixed by the problem: B=8 images, 128x128 patches, D=1024,
// merge=2 -> M=32768 merged tokens, K=4096, N=1024.
//
// merged[n, 4d+2ki+kj] = X[b*16384 + (2i+ki)*128 + (2j+kj), d]
//   with b=n>>12, i=(n&4095)>>6, j=n&63
// out[n, dout] = sum_k merged[n,k] * W[dout,k]

#define MDIM 32768
#define NDIM 1024
#define KDIM 4096

#define BM 128
#define BN 128
#define BK 16
#define TM 8
#define TN 8
#define NTHREADS 256

__global__ __launch_bounds__(NTHREADS, 2)
void merger_sgemm(const float* __restrict__ X,
                  const float* __restrict__ W,
                  float* __restrict__ O)
{
    __shared__ float As[BK][BM];        // [k][m]
    __shared__ float Bs[BK][BN + 4];    // [k][dout], +4 pad (keeps float4 alignment)

    const int tid = threadIdx.x;
    const int bn  = blockIdx.x;   // 8 N-tiles (fastest -> wave shares A slice in L2)
    const int bm  = blockIdx.y;   // 256 M-tiles

    const int tx = tid & 15;      // 16 cols of threads
    const int ty = tid >> 4;      // 16 rows of threads

    const int m_base = bm * BM;
    const int n_base = bn * BN;

    // Precompute gather source rows for this thread's two A-tile loads.
    // idx = tid + it*256 over [0,512): c = idx&3 (c = 2*ki+kj), m = idx>>2.
    int a_m[2], a_c[2];
    long a_row[2];
#pragma unroll
    for (int it = 0; it < 2; ++it) {
        int idx = tid + it * NTHREADS;
        int c = idx & 3;
        int m = idx >> 2;
        int n = m_base + m;
        int b = n >> 12;
        int t = n & 4095;
        int i = t >> 6;
        int j = t & 63;
        int ki = c >> 1;
        int kj = c & 1;
        int srow = (b << 14) + ((2 * i + ki) << 7) + (2 * j + kj);
        a_row[it] = (long)srow * 1024;
        a_m[it] = m;
        a_c[it] = c;
    }

    float acc[TM][TN];
#pragma unroll
    for (int r = 0; r < TM; ++r)
#pragma unroll
        for (int c = 0; c < TN; ++c) acc[r][c] = 0.0f;

    for (int kk = 0; kk < KDIM; kk += BK) {
        const int d0 = kk >> 2;   // feature-d base for this K chunk

        // ---- A tile: one float4 covers k-local = c, c+4, c+8, c+12 at column m
#pragma unroll
        for (int it = 0; it < 2; ++it) {
            float4 v = *reinterpret_cast<const float4*>(X + a_row[it] + d0);
            int c = a_c[it], m = a_m[it];
            As[c + 0][m]  = v.x;
            As[c + 4][m]  = v.y;
            As[c + 8][m]  = v.z;
            As[c + 12][m] = v.w;
        }

        // ---- B tile: W[dout, kk..kk+15]; 4 consecutive threads cover one dout row (64B)
#pragma unroll
        for (int it = 0; it < 2; ++it) {
            int idx = tid + it * NTHREADS;
            int kq = idx & 3;
            int dl = idx >> 2;
            float4 v = *reinterpret_cast<const float4*>(
                W + (long)(n_base + dl) * KDIM + kk + kq * 4);
            Bs[kq * 4 + 0][dl] = v.x;
            Bs[kq * 4 + 1][dl] = v.y;
            Bs[kq * 4 + 2][dl] = v.z;
            Bs[kq * 4 + 3][dl] = v.w;
        }

        __syncthreads();

#pragma unroll
        for (int kl = 0; kl < BK; ++kl) {
            float a[TM], b[TN];
            *reinterpret_cast<float4*>(&a[0]) =
                *reinterpret_cast<const float4*>(&As[kl][ty * TM]);
            *reinterpret_cast<float4*>(&a[4]) =
                *reinterpret_cast<const float4*>(&As[kl][ty * TM + 4]);
            *reinterpret_cast<float4*>(&b[0]) =
                *reinterpret_cast<const float4*>(&Bs[kl][tx * TN]);
            *reinterpret_cast<float4*>(&b[4]) =
                *reinterpret_cast<const float4*>(&Bs[kl][tx * TN + 4]);
#pragma unroll
            for (int r = 0; r < TM; ++r)
#pragma unroll
                for (int c = 0; c < TN; ++c)
                    acc[r][c] += a[r] * b[c];
        }

        __syncthreads();
    }

    // ---- epilogue: float4 stores
#pragma unroll
    for (int r = 0; r < TM; ++r) {
        int row = m_base + ty * TM + r;
        float* op = O + (long)row * NDIM + n_base + tx * TN;
        float4 v0 = make_float4(acc[r][0], acc[r][1], acc[r][2], acc[r][3]);
        float4 v1 = make_float4(acc[r][4], acc[r][5], acc[r][6], acc[r][7]);
        *reinterpret_cast<float4*>(op)     = v0;
        *reinterpret_cast<float4*>(op + 4) = v1;
    }
}

extern "C" void kernel_launch(void* const* d_in, const int* in_sizes, int n_in,
                              void* d_out, int out_size)
{
    const float* X = (const float*)d_in[0];   // image_features (1, 131072, 1024) fp32
    // d_in[1]: image_sizes (8,2) int32 — geometry is fixed (all 1792px), hardcoded
    const float* W = (const float*)d_in[2];   // (1024, 4096) fp32
    float* O = (float*)d_out;                 // (1, 32768, 1024) fp32

    dim3 grid(NDIM / BN, MDIM / BM);          // (8, 256)
    merger_sgemm<<<grid, NTHREADS>>>(X, W, O);
}